// round 16
// baseline (speedup 1.0000x reference)
#include <cuda_runtime.h>
#include <cuda_fp16.h>
#include <math.h>
#include <stdint.h>

constexpr int Bb = 4, LP = 768, LE = 256, Lt = 1024;
constexpr int DP = 2048, DE = 1024, Hh = 8, HD = 256, HH = 2048;
constexpr int NQKV = HH + 2 * HD;  // 2560

// fp32 scratch
__device__ __align__(1024) float g_QKV[(size_t)Bb * Lt * NQKV];

// packed fp16 operands, K-major rows [R][K]
__device__ __align__(1024) __half hA_pali[(size_t)Bb * LP * DP];
__device__ __align__(1024) __half hA_exp [(size_t)Bb * LE * DE];
__device__ __align__(1024) __half hA_Q   [(size_t)Bb * Hh * Lt * HD];
__device__ __align__(1024) __half hAO    [(size_t)Bb * Lt * HH];
__device__ __align__(1024) __half hB_qkvp[(size_t)NQKV * DP];
__device__ __align__(1024) __half hB_qkve[(size_t)NQKV * DE];
__device__ __align__(1024) __half hB_K   [(size_t)Bb * Lt * HD];
__device__ __align__(1024) __half hB_V   [(size_t)Bb * HD * Lt];
__device__ __align__(1024) __half hB_wop [(size_t)DP * HH];
__device__ __align__(1024) __half hB_woe [(size_t)DE * HH];

__device__ __forceinline__ uint32_t s2u(const void* p) {
    uint32_t a;
    asm("{ .reg .u64 t; cvta.to.shared.u64 t, %1; cvt.u32.u64 %0, t; }" : "=r"(a) : "l"(p));
    return a;
}

#define CP_ASYNC16(saddr, gaddr) \
    asm volatile("cp.async.cg.shared.global [%0], [%1], 16;" :: "r"(saddr), "l"(gaddr))
#define CP_COMMIT() asm volatile("cp.async.commit_group;")
#define CP_WAIT(n)  asm volatile("cp.async.wait_group %0;" :: "n"(n))

#define LDSM4(r, addr)                                                       \
    asm volatile("ldmatrix.sync.aligned.m8n8.x4.shared.b16 {%0,%1,%2,%3}, [%4];" \
        : "=r"((r)[0]), "=r"((r)[1]), "=r"((r)[2]), "=r"((r)[3]) : "r"(addr))

#define MMA16816(c, a, b0, b1)                                               \
    asm volatile("mma.sync.aligned.m16n8k16.row.col.f32.f16.f16.f32 "        \
        "{%0,%1,%2,%3},{%4,%5,%6,%7},{%8,%9},{%0,%1,%2,%3};"                 \
        : "+f"((c)[0]), "+f"((c)[1]), "+f"((c)[2]), "+f"((c)[3])             \
        : "r"((a)[0]), "r"((a)[1]), "r"((a)[2]), "r"((a)[3]), "r"(b0), "r"(b1))

// ===========================================================================
// Persistent multi-zone HMMA GEMM (projections): 128x128 tiles, BK=64,
// 8 warps of 32x64, 3-stage ring, batched A frags, smem-restaged epilogue.
// ===========================================================================
constexpr int GEMM_SMEM = 98304;

struct GZone {
    const __half* A; const __half* B; float* C;
    long long sAz, sBz, cso;
    int K, zshB, ldc, out_half, nt, mt, tstart;
};
struct GZones { GZone z[2]; int nz; int total; };

__global__ void __launch_bounds__(256, 2) gemm_hmma(GZones gz)
{
    extern __shared__ __align__(1024) char smem[];
    const uint32_t sbase = s2u(smem);
    float* scf = reinterpret_cast<float*>(smem);
    const int t = threadIdx.x;
    const int lrow = t >> 3, lc = t & 7;
    const int wid = t >> 5, lane = t & 31;
    const int wm = wid >> 1, wn = wid & 1;
    const int a_r = lane & 15, a_c = lane >> 4;
    const int b_r = (lane & 7) + ((lane >> 4) << 3), b_c = (lane >> 3) & 1;

    for (int tix = blockIdx.x; tix < gz.total; tix += gridDim.x) {
        const int zi = (gz.nz > 1 && tix >= gz.z[1].tstart) ? 1 : 0;
        const GZone& d = gz.z[zi];
        const int lt2 = tix - d.tstart;
        const int bx = lt2 % d.nt;
        const int tmp = lt2 / d.nt;
        const int by = tmp % d.mt, bz = tmp / d.mt;
        const int K = d.K;
        const int nch = K >> 6;

        const __half* Ag = d.A + (long long)bz * d.sAz + (long long)by * 128 * K;
        const __half* Bg = d.B + (long long)(bz >> d.zshB) * d.sBz + (long long)bx * 128 * K;

        float acc[2][8][4];
#pragma unroll
        for (int i = 0; i < 2; i++)
#pragma unroll
            for (int j = 0; j < 8; j++)
#pragma unroll
                for (int k = 0; k < 4; k++) acc[i][j][k] = 0.f;

#define STAGE(s, k0) do {                                                    \
    uint32_t _sA = sbase + (s) * 32768;                                      \
    uint32_t _sB = _sA + 16384;                                              \
    _Pragma("unroll")                                                        \
    for (int _i = 0; _i < 4; _i++) {                                         \
        int _r = lrow + _i * 32;                                             \
        uint32_t _sw = ((uint32_t)(lc ^ (_r & 7))) << 4;                     \
        CP_ASYNC16(_sA + _r * 128 + _sw, Ag + (long long)_r * K + (k0) + lc * 8); \
        CP_ASYNC16(_sB + _r * 128 + _sw, Bg + (long long)_r * K + (k0) + lc * 8); \
    }                                                                        \
    CP_COMMIT();                                                             \
} while (0)

        __syncthreads();
        STAGE(0, 0);
        if (nch > 1) STAGE(1, 64);

        int slot = 0, slot2 = (nch > 2) ? 2 : 0;
        for (int ch = 0; ch < nch; ch++) {
            if (ch + 1 < nch) CP_WAIT(1); else CP_WAIT(0);
            __syncthreads();
            if (ch + 2 < nch) {
                STAGE(slot2, (ch + 2) << 6);
                slot2 = (slot2 == 2) ? 0 : slot2 + 1;
            }
            uint32_t sA = sbase + slot * 32768;
            uint32_t sB = sA + 16384;
            slot = (slot == 2) ? 0 : slot + 1;

            uint32_t a[4][2][4];
#pragma unroll
            for (int ks = 0; ks < 4; ks++) {
                const int kc = ks << 1;
#pragma unroll
                for (int mt2 = 0; mt2 < 2; mt2++) {
                    int r = wm * 32 + mt2 * 16 + a_r;
                    LDSM4(a[ks][mt2], sA + r * 128 + ((uint32_t)((kc + a_c) ^ (r & 7)) << 4));
                }
            }
#pragma unroll
            for (int ks = 0; ks < 4; ks++) {
                const int kc = ks << 1;
                uint32_t b[4][4];
#pragma unroll
                for (int nt2 = 0; nt2 < 4; nt2++) {
                    int n = wn * 64 + nt2 * 16 + b_r;
                    LDSM4(b[nt2], sB + n * 128 + ((uint32_t)((kc + b_c) ^ (n & 7)) << 4));
                }
#pragma unroll
                for (int mt2 = 0; mt2 < 2; mt2++)
#pragma unroll
                    for (int nt = 0; nt < 8; nt++)
                        MMA16816(acc[mt2][nt], a[ks][mt2],
                                 b[nt >> 1][(nt & 1) * 2], b[nt >> 1][(nt & 1) * 2 + 1]);
            }
        }
#undef STAGE

        __syncthreads();
        const int g = lane >> 2, tig = lane & 3;
#pragma unroll
        for (int mt2 = 0; mt2 < 2; mt2++) {
#pragma unroll
            for (int h2 = 0; h2 < 2; h2++) {
                int row = wm * 32 + mt2 * 16 + g + h2 * 8;
                float* srow = scf + row * 132 + wn * 64 + tig * 2;
#pragma unroll
                for (int nt = 0; nt < 8; nt++) {
                    srow[nt * 8]     = acc[mt2][nt][h2 * 2 + 0];
                    srow[nt * 8 + 1] = acc[mt2][nt][h2 * 2 + 1];
                }
            }
        }
        __syncthreads();

        const long long coff = (long long)bz * d.cso;
        const long long cbase = (long long)by * 128 * d.ldc + (long long)bx * 128;

        if (d.out_half) {
            __half* cp = reinterpret_cast<__half*>(d.C) + coff + cbase;
#pragma unroll
            for (int j = 0; j < 8; j++) {
                int idx = j * 256 + t;
                int r = idx >> 4, h8 = (idx & 15) * 8;
                const float* sr = scf + r * 132 + h8;
                __half2 q0 = __halves2half2(__float2half_rn(sr[0]), __float2half_rn(sr[1]));
                __half2 q1 = __halves2half2(__float2half_rn(sr[2]), __float2half_rn(sr[3]));
                __half2 q2 = __halves2half2(__float2half_rn(sr[4]), __float2half_rn(sr[5]));
                __half2 q3 = __halves2half2(__float2half_rn(sr[6]), __float2half_rn(sr[7]));
                uint4 w;
                w.x = *reinterpret_cast<uint32_t*>(&q0);
                w.y = *reinterpret_cast<uint32_t*>(&q1);
                w.z = *reinterpret_cast<uint32_t*>(&q2);
                w.w = *reinterpret_cast<uint32_t*>(&q3);
                *reinterpret_cast<uint4*>(cp + (long long)r * d.ldc + h8) = w;
            }
        } else {
            float* cp = d.C + coff + cbase;
#pragma unroll
            for (int j = 0; j < 16; j++) {
                int idx = j * 256 + t;
                int r = idx >> 5, c4 = (idx & 31) * 4;
                const float* sr = scf + r * 132 + c4;
                *reinterpret_cast<float4*>(cp + (long long)r * d.ldc + c4) =
                    make_float4(sr[0], sr[1], sr[2], sr[3]);
            }
        }
    }
}

// ===========================================================================
// Fused flash attention: per unit (b,h,qblk of 128 rows), loop 8 k-blocks.
// 512 threads (16 warps, 4x4). S via 3-stage ring (Q,K from gmem), mask LDG,
// online softmax (fp32 stats), P via swizzled smem, PV from prefetched V.
// ===========================================================================
constexpr int FA_V   = 98304;    // V tile 256x128 fp16 (64KB), swizzled 256B rows
constexpr int FA_P   = 163840;   // P tile 128x128 fp16 (32KB), swizzled 256B rows
constexpr int FA_PM  = 196608;   // float[512] partials
constexpr int FA_M   = 198656;   // float[128]
constexpr int FA_L   = 199168;   // float[128]
constexpr int FA_AL  = 199680;   // float[128]
constexpr int FA_SMEM = 200192;

__global__ void __launch_bounds__(512, 1) flash_attn(
    const __half* __restrict__ aQ, const __half* __restrict__ bK,
    const __half* __restrict__ bV, const float* __restrict__ mask,
    __half* __restrict__ AO)
{
    extern __shared__ __align__(1024) char smem[];
    const uint32_t sb = s2u(smem);
    float* sm_pm = reinterpret_cast<float*>(smem + FA_PM);
    float* sm_m  = reinterpret_cast<float*>(smem + FA_M);
    float* sm_l  = reinterpret_cast<float*>(smem + FA_L);
    float* sm_al = reinterpret_cast<float*>(smem + FA_AL);

    const int t = threadIdx.x, wid = t >> 5, lane = t & 31;
    const int wm = wid >> 2, wn = wid & 3;
    const int lrow = t >> 3, lc = t & 7;
    const int a_r = lane & 15, a_c = lane >> 4;
    const int b_r = (lane & 7) + ((lane >> 4) << 3), b_c = (lane >> 3) & 1;
    const int g = lane >> 2, tig = lane & 3;

    for (int unit = blockIdx.x; unit < 256; unit += gridDim.x) {
        const int z = unit >> 3, qb = unit & 7;
        const int b = z >> 3, h = z & 7;
        const __half* Qg = aQ + ((long long)z * Lt + qb * 128) * HD;
        const float* Mg = mask + (long long)b * Lt * Lt + (long long)qb * 128 * Lt;

        __syncthreads();
        if (t < 128) { sm_m[t] = -1e30f; sm_l[t] = 0.f; }
        float accO[2][8][4];
#pragma unroll
        for (int i = 0; i < 2; i++)
#pragma unroll
            for (int j = 0; j < 8; j++)
#pragma unroll
                for (int k = 0; k < 4; k++) accO[i][j][k] = 0.f;
        __syncthreads();

        for (int kb = 0; kb < 8; kb++) {
            const __half* Kg = bK + ((long long)b * Lt + kb * 128) * HD;

#define FSTAGE(s, k0) do {                                                   \
    uint32_t _sA = sb + (s) * 32768;                                         \
    uint32_t _sB = _sA + 16384;                                              \
    _Pragma("unroll")                                                        \
    for (int _i = 0; _i < 2; _i++) {                                         \
        int _r = lrow + _i * 64;                                             \
        uint32_t _sw = ((uint32_t)(lc ^ (_r & 7))) << 4;                     \
        CP_ASYNC16(_sA + _r * 128 + _sw, Qg + (long long)_r * HD + (k0) + lc * 8); \
        CP_ASYNC16(_sB + _r * 128 + _sw, Kg + (long long)_r * HD + (k0) + lc * 8); \
    }                                                                        \
    CP_COMMIT();                                                             \
} while (0)

            FSTAGE(0, 0);
            FSTAGE(1, 64);
            // V prefetch (committed 3rd)
            {
                int vr = t >> 1;
                const __half* vsrc = bV + ((long long)b * HD + vr) * Lt + kb * 128;
#pragma unroll
                for (int j = 0; j < 8; j++) {
                    int cc = (t & 1) * 8 + j;
                    uint32_t sw = (uint32_t)((cc & 8) | ((cc ^ (vr & 7)) & 7));
                    CP_ASYNC16(sb + FA_V + vr * 256 + sw * 16, vsrc + cc * 8);
                }
                CP_COMMIT();
            }

            float accS[2][4][4];
#pragma unroll
            for (int i = 0; i < 2; i++)
#pragma unroll
                for (int j = 0; j < 4; j++)
#pragma unroll
                    for (int k = 0; k < 4; k++) accS[i][j][k] = 0.f;

            // 4 K-chunks; commits: c0,c1,V,(c2),(c3)
#pragma unroll
            for (int ch = 0; ch < 4; ch++) {
                if (ch <= 1) CP_WAIT(2);
                else if (ch == 2) CP_WAIT(1);
                else CP_WAIT(0);
                __syncthreads();
                if (ch == 0) FSTAGE(2, 128);
                if (ch == 1) FSTAGE(0, 192);
                int slot = (ch == 3) ? 0 : ch;
                uint32_t sA = sb + slot * 32768;
                uint32_t sB = sA + 16384;
#pragma unroll
                for (int ks = 0; ks < 4; ks++) {
                    const int kc = ks << 1;
                    uint32_t af[2][4], bf[2][4];
#pragma unroll
                    for (int mt = 0; mt < 2; mt++) {
                        int r = wm * 32 + mt * 16 + a_r;
                        LDSM4(af[mt], sA + r * 128 + ((uint32_t)((kc + a_c) ^ (r & 7)) << 4));
                    }
#pragma unroll
                    for (int nt2 = 0; nt2 < 2; nt2++) {
                        int n = wn * 32 + nt2 * 16 + b_r;
                        LDSM4(bf[nt2], sB + n * 128 + ((uint32_t)((kc + b_c) ^ (n & 7)) << 4));
                    }
#pragma unroll
                    for (int mt = 0; mt < 2; mt++)
#pragma unroll
                        for (int nt = 0; nt < 4; nt++)
                            MMA16816(accS[mt][nt], af[mt],
                                     bf[nt >> 1][(nt & 1) * 2], bf[nt >> 1][(nt & 1) * 2 + 1]);
                }
            }
#undef FSTAGE

            // ---- scale + mask + local row max ----
#pragma unroll
            for (int mt = 0; mt < 2; mt++) {
#pragma unroll
                for (int h2 = 0; h2 < 2; h2++) {
                    int row = wm * 32 + mt * 16 + g + h2 * 8;
                    const float* mrow = Mg + (long long)row * Lt + kb * 128 + wn * 32 + tig * 2;
                    float vmax = -1e30f;
#pragma unroll
                    for (int nt = 0; nt < 4; nt++) {
                        float2 mv = *reinterpret_cast<const float2*>(mrow + nt * 8);
                        float s0 = accS[mt][nt][h2 * 2 + 0] * 0.0625f + mv.x;
                        float s1 = accS[mt][nt][h2 * 2 + 1] * 0.0625f + mv.y;
                        accS[mt][nt][h2 * 2 + 0] = s0;
                        accS[mt][nt][h2 * 2 + 1] = s1;
                        vmax = fmaxf(vmax, fmaxf(s0, s1));
                    }
                    vmax = fmaxf(vmax, __shfl_xor_sync(0xFFFFFFFFu, vmax, 1));
                    vmax = fmaxf(vmax, __shfl_xor_sync(0xFFFFFFFFu, vmax, 2));
                    if (tig == 0) sm_pm[row * 4 + wn] = vmax;
                }
            }
            __syncthreads();
            if (t < 128) {
                float mb = fmaxf(fmaxf(sm_pm[t * 4], sm_pm[t * 4 + 1]),
                                 fmaxf(sm_pm[t * 4 + 2], sm_pm[t * 4 + 3]));
                float mo = sm_m[t];
                float mn = fmaxf(mo, mb);
                sm_al[t] = __expf(mo - mn);
                sm_m[t] = mn;
            }
            __syncthreads();

            // ---- p = exp(s - m), store P, partial sums; rescale O ----
#pragma unroll
            for (int mt = 0; mt < 2; mt++) {
#pragma unroll
                for (int h2 = 0; h2 < 2; h2++) {
                    int row = wm * 32 + mt * 16 + g + h2 * 8;
                    float mn = sm_m[row];
                    float psum = 0.f;
#pragma unroll
                    for (int nt = 0; nt < 4; nt++) {
                        float p0 = __expf(accS[mt][nt][h2 * 2 + 0] - mn);
                        float p1 = __expf(accS[mt][nt][h2 * 2 + 1] - mn);
                        psum += p0 + p1;
                        __half2 hp = __halves2half2(__float2half_rn(p0), __float2half_rn(p1));
                        int cc = wn * 4 + nt;
                        uint32_t sw = (uint32_t)((cc & 8) | ((cc ^ (row & 7)) & 7));
                        *reinterpret_cast<uint32_t*>(smem + FA_P + row * 256 + sw * 16 + tig * 4) =
                            *reinterpret_cast<uint32_t*>(&hp);
                    }
                    psum += __shfl_xor_sync(0xFFFFFFFFu, psum, 1);
                    psum += __shfl_xor_sync(0xFFFFFFFFu, psum, 2);
                    if (tig == 0) sm_pm[row * 4 + wn] = psum;
                    float al = sm_al[row];
#pragma unroll
                    for (int nt = 0; nt < 8; nt++) {
                        accO[mt][nt][h2 * 2 + 0] *= al;
                        accO[mt][nt][h2 * 2 + 1] *= al;
                    }
                }
            }
            __syncthreads();
            if (t < 128) {
                sm_l[t] = sm_l[t] * sm_al[t] +
                          sm_pm[t * 4] + sm_pm[t * 4 + 1] + sm_pm[t * 4 + 2] + sm_pm[t * 4 + 3];
            }

            // ---- PV: O += P(128x128) * V^T ----
#pragma unroll
            for (int ks = 0; ks < 8; ks++) {
                uint32_t pf[2][4], vf[4][4];
#pragma unroll
                for (int mt = 0; mt < 2; mt++) {
                    int r = wm * 32 + mt * 16 + a_r;
                    int cc = ks * 2 + a_c;
                    uint32_t sw = (uint32_t)((cc & 8) | ((cc ^ (r & 7)) & 7));
                    LDSM4(pf[mt], sb + FA_P + r * 256 + sw * 16);
                }
#pragma unroll
                for (int nt2 = 0; nt2 < 4; nt2++) {
                    int dd = wn * 64 + nt2 * 16 + b_r;
                    int cc = ks * 2 + b_c;
                    uint32_t sw = (uint32_t)((cc & 8) | ((cc ^ (dd & 7)) & 7));
                    LDSM4(vf[nt2], sb + FA_V + dd * 256 + sw * 16);
                }
#pragma unroll
                for (int mt = 0; mt < 2; mt++)
#pragma unroll
                    for (int nt = 0; nt < 8; nt++)
                        MMA16816(accO[mt][nt], pf[mt],
                                 vf[nt >> 1][(nt & 1) * 2], vf[nt >> 1][(nt & 1) * 2 + 1]);
            }
            __syncthreads();   // protect V/P/ring for next iteration
        }

        // ---- epilogue: O /= l, restage fp16 via ring smem, coalesced out ----
#pragma unroll
        for (int mt = 0; mt < 2; mt++) {
#pragma unroll
            for (int h2 = 0; h2 < 2; h2++) {
                int row = wm * 32 + mt * 16 + g + h2 * 8;
                float il = 1.0f / sm_l[row];
                __half* srow = reinterpret_cast<__half*>(smem) + row * 256 + wn * 64 + tig * 2;
#pragma unroll
                for (int nt = 0; nt < 8; nt++) {
                    __half2 hv = __halves2half2(
                        __float2half_rn(accO[mt][nt][h2 * 2 + 0] * il),
                        __float2half_rn(accO[mt][nt][h2 * 2 + 1] * il));
                    *reinterpret_cast<__half2*>(srow + nt * 8) = hv;
                }
            }
        }
        __syncthreads();
        {
            // 128 rows x 512B = 4096 uint4; 32 uint4 per row  (R15 bug: was 16)
            __half* dst = AO + ((long long)b * Lt + qb * 128) * HH + h * HD;
#pragma unroll
            for (int j = 0; j < 8; j++) {
                int idx = j * 512 + t;
                int r = idx >> 5, cc = (idx & 31) * 16;   // byte offset in row
                uint4 w = *reinterpret_cast<uint4*>(smem + r * 512 + cc);
                *reinterpret_cast<uint4*>(dst + (long long)r * HH + cc / 2) = w;
            }
        }
    }
}

// ===========================================================================
// Megapack: embeds (direct fp16) + weights (smem transpose fp16)
// ===========================================================================
struct Seg {
    const float* src; __half* dst;
    int nblocks; int mode; int R; int K;
};
struct SegTable { Seg s[10]; };

__global__ void __launch_bounds__(256) megapack(SegTable st)
{
    __shared__ float sm[32][33];
    int b = blockIdx.x, si = 0;
    while (b >= st.s[si].nblocks) { b -= st.s[si].nblocks; si++; }
    const Seg sg = st.s[si];

    if (sg.mode == 0) {
        long long idx = (long long)b * 256 + threadIdx.x;
        int K8 = sg.K >> 3;
        long long items = (long long)sg.R * K8;
        if (idx >= items) return;
        int kc = (int)(idx % K8);
        long long r = idx / K8;
        const float* sp = sg.src + r * (long long)sg.K + kc * 8;
        float4 x = *reinterpret_cast<const float4*>(sp);
        float4 y = *reinterpret_cast<const float4*>(sp + 4);
        float v[8] = {x.x, x.y, x.z, x.w, y.x, y.y, y.z, y.w};
        unsigned short o[8];
#pragma unroll
        for (int i = 0; i < 8; i++) o[i] = __half_as_ushort(__float2half_rn(v[i]));
        uint4 w;
        w.x = o[0] | ((uint32_t)o[1] << 16); w.y = o[2] | ((uint32_t)o[3] << 16);
        w.z = o[4] | ((uint32_t)o[5] << 16); w.w = o[6] | ((uint32_t)o[7] << 16);
        *reinterpret_cast<uint4*>(sg.dst + r * (long long)sg.K + kc * 8) = w;
    } else {
        int nx = sg.K >> 5;
        int k0 = (b % nx) * 32, n0 = (b / nx) * 32;
        int tx = threadIdx.x & 31, ty = threadIdx.x >> 5;
#pragma unroll
        for (int i = 0; i < 4; i++)
            sm[ty + 8 * i][tx] = sg.src[(long long)(k0 + ty + 8 * i) * sg.R + n0 + tx];
        __syncthreads();
#pragma unroll
        for (int i = 0; i < 4; i++) {
            int n = n0 + ty + 8 * i;
            sg.dst[(long long)n * sg.K + k0 + tx] = __float2half_rn(sm[tx][ty + 8 * i]);
        }
    }
}

// ===========================================================================
// Merged RoPE-pack (blocks [0,2048)) + V transpose-pack (blocks [2048,3072))
// ===========================================================================
__global__ void __launch_bounds__(256) ropevt(
    const float* __restrict__ QKV, const int* __restrict__ pos,
    __half* __restrict__ aQ, __half* __restrict__ bK, __half* __restrict__ bV)
{
    if (blockIdx.x < 2048) {
        const int bl = blockIdx.x * 2 + (threadIdx.x >> 7);
        const int bidx = bl >> 10, l = bl & 1023;
        const int i = threadIdx.x & 127;
        const float p = (float)pos[bl];
        const float inv = powf(10000.0f, -(float)i * (1.0f / 128.0f));
        float s, c;
        sincosf(p * inv, &s, &c);

        const float* row = QKV + (long long)bl * NQKV;
#pragma unroll
        for (int h = 0; h < Hh; h++) {
            float x1 = row[h * HD + i], x2 = row[h * HD + 128 + i];
            __half* q = aQ + (((long long)(bidx * Hh + h) * Lt + l) * HD);
            q[i]       = __float2half_rn(x1 * c - x2 * s);
            q[128 + i] = __float2half_rn(x2 * c + x1 * s);
        }
        float x1 = row[HH + i], x2 = row[HH + 128 + i];
        __half* kd = bK + ((long long)bidx * Lt + l) * HD;
        kd[i]       = __float2half_rn(x1 * c - x2 * s);
        kd[128 + i] = __float2half_rn(x2 * c + x1 * s);
    } else {
        __shared__ float sm[32][33];
        int vb = blockIdx.x - 2048;
        const int bidx = vb >> 8;
        int rem = vb & 255;
        const int l0 = (rem & 31) * 32, d0 = (rem >> 5) * 32;
        const int tx = threadIdx.x & 31, ty = threadIdx.x >> 5;
#pragma unroll
        for (int i = 0; i < 4; i++)
            sm[ty + 8 * i][tx] = QKV[((long long)bidx * Lt + l0 + ty + 8 * i) * NQKV + HH + HD + d0 + tx];
        __syncthreads();
#pragma unroll
        for (int i = 0; i < 4; i++) {
            int d = d0 + ty + 8 * i;
            bV[((long long)bidx * HD + d) * Lt + l0 + tx] = __float2half_rn(sm[tx][ty + 8 * i]);
        }
    }
}

// ===========================================================================
// Host
// ===========================================================================
static GZone mkzone(const __half* A, const __half* B, void* C,
                    int nt, int mt, int K, long long sAz, long long sBz,
                    int zshB, long long cso, int ldc, int out_half)
{
    GZone z;
    z.A = A; z.B = B; z.C = (float*)C;
    z.sAz = sAz; z.sBz = sBz; z.cso = cso;
    z.K = K; z.zshB = zshB; z.ldc = ldc; z.out_half = out_half;
    z.nt = nt; z.mt = mt; z.tstart = 0;
    return z;
}

static void launch_zones(GZone z0, int n0, GZone z1, int n1, int nz)
{
    GZones g;
    z0.tstart = 0;
    g.z[0] = z0;
    int total = n0;
    if (nz > 1) { z1.tstart = total; g.z[1] = z1; total += n1; }
    else        { g.z[1] = z0; }
    g.nz = nz; g.total = total;
    int grid = total < 296 ? total : 296;
    gemm_hmma<<<grid, 256, GEMM_SMEM>>>(g);
}

extern "C" void kernel_launch(void* const* d_in, const int* in_sizes, int n_in,
                              void* d_out, int out_size)
{
    const float* pali   = (const float*)d_in[0];
    const float* expert = (const float*)d_in[1];
    const int*   pos    = (const int*)d_in[2];
    const float* mask   = (const float*)d_in[3];
    const float* wq_p = (const float*)d_in[5];
    const float* wk_p = (const float*)d_in[6];
    const float* wv_p = (const float*)d_in[7];
    const float* wo_p = (const float*)d_in[8];
    const float* wq_e = (const float*)d_in[9];
    const float* wk_e = (const float*)d_in[10];
    const float* wv_e = (const float*)d_in[11];
    const float* wo_e = (const float*)d_in[12];
    float* out = (float*)d_out;

    cudaFuncSetAttribute(gemm_hmma, cudaFuncAttributeMaxDynamicSharedMemorySize, GEMM_SMEM);
    cudaFuncSetAttribute(flash_attn, cudaFuncAttributeMaxDynamicSharedMemorySize, FA_SMEM);

    float* QKV;
    cudaGetSymbolAddress((void**)&QKV, g_QKV);
    __half *aP, *aE, *aQ, *AO, *bQP, *bQE, *bK, *bV, *bWP, *bWE;
    cudaGetSymbolAddress((void**)&aP,  hA_pali);
    cudaGetSymbolAddress((void**)&aE,  hA_exp);
    cudaGetSymbolAddress((void**)&aQ,  hA_Q);
    cudaGetSymbolAddress((void**)&AO,  hAO);
    cudaGetSymbolAddress((void**)&bQP, hB_qkvp);
    cudaGetSymbolAddress((void**)&bQE, hB_qkve);
    cudaGetSymbolAddress((void**)&bK,  hB_K);
    cudaGetSymbolAddress((void**)&bV,  hB_V);
    cudaGetSymbolAddress((void**)&bWP, hB_wop);
    cudaGetSymbolAddress((void**)&bWE, hB_woe);

    SegTable st;
    int nb = 0;
    auto setd = [&](int i, const float* s, __half* d, int R, int K) {
        st.s[i] = {s, d, (int)(((long long)R * K / 8 + 255) / 256), 0, R, K};
        nb += st.s[i].nblocks;
    };
    auto sett = [&](int i, const float* s, __half* d, int N, int K) {
        st.s[i] = {s, d, (K / 32) * (N / 32), 1, N, K};
        nb += st.s[i].nblocks;
    };
    setd(0, pali,   aP, Bb * LP, DP);
    setd(1, expert, aE, Bb * LE, DE);
    sett(2, wq_p, bQP,                      HH, DP);
    sett(3, wk_p, bQP + (long long)HH * DP,        HD, DP);
    sett(4, wv_p, bQP + (long long)(HH + HD) * DP, HD, DP);
    sett(5, wq_e, bQE,                      HH, DE);
    sett(6, wk_e, bQE + (long long)HH * DE,        HD, DE);
    sett(7, wv_e, bQE + (long long)(HH + HD) * DE, HD, DE);
    sett(8, wo_p, bWP, DP, HH);
    sett(9, wo_e, bWE, DE, HH);
    megapack<<<nb, 256>>>(st);                                   // launch 1

    // QKV projections (merged)                                  // launch 2
    {
        GZone zp = mkzone(aP, bQP, QKV, NQKV / 128, LP / 128, DP,
                          (long long)LP * DP, 0, 31, (long long)Lt * NQKV, NQKV, 0);
        GZone ze = mkzone(aE, bQE, QKV + (long long)LP * NQKV, NQKV / 128, LE / 128, DE,
                          (long long)LE * DE, 0, 31, (long long)Lt * NQKV, NQKV, 0);
        launch_zones(zp, (NQKV / 128) * (LP / 128) * Bb, ze, (NQKV / 128) * (LE / 128) * Bb, 2);
    }

    // RoPE + Q/K pack + V transpose (merged)                    // launch 3
    ropevt<<<3072, 256>>>(QKV, pos, aQ, bK, bV);

    // Fused flash attention                                     // launch 4
    flash_attn<<<148, 512, FA_SMEM>>>(aQ, bK, bV, mask, AO);

    // Output projections (merged)                               // launch 5
    {
        GZone zo = mkzone(AO, bWP, out, DP / 128, LP / 128, HH,
                          (long long)Lt * HH, 0, 31, (long long)LP * DP, DP, 0);
        GZone ze = mkzone(AO + (long long)LP * HH, bWE, out + (long long)Bb * LP * DP,
                          DE / 128, LE / 128, HH,
                          (long long)Lt * HH, 0, 31, (long long)LE * DE, DE, 0);
        launch_zones(zo, (DP / 128) * (LP / 128) * Bb, ze, (DE / 128) * (LE / 128) * Bb, 2);
    }
}

// round 17
// speedup vs baseline: 1.0685x; 1.0685x over previous
#include <cuda_runtime.h>
#include <cuda_fp16.h>
#include <math.h>
#include <stdint.h>

constexpr int Bb = 4, LP = 768, LE = 256, Lt = 1024;
constexpr int DP = 2048, DE = 1024, Hh = 8, HD = 256, HH = 2048;
constexpr int NQKV = HH + 2 * HD;  // 2560

// fp32 scratch (scores only)
__device__ __align__(1024) float g_S[(size_t)Bb * Hh * Lt * Lt];

// fp16 QKV intermediate + packed fp16 operands, K-major rows [R][K]
__device__ __align__(1024) __half hQKV  [(size_t)Bb * Lt * NQKV];
__device__ __align__(1024) __half hA_pali[(size_t)Bb * LP * DP];
__device__ __align__(1024) __half hA_exp [(size_t)Bb * LE * DE];
__device__ __align__(1024) __half hA_Q   [(size_t)Bb * Hh * Lt * HD];
__device__ __align__(1024) __half hA_P   [(size_t)Bb * Hh * Lt * Lt];
__device__ __align__(1024) __half hAO    [(size_t)Bb * Lt * HH];
__device__ __align__(1024) __half hB_qkvp[(size_t)NQKV * DP];
__device__ __align__(1024) __half hB_qkve[(size_t)NQKV * DE];
__device__ __align__(1024) __half hB_K   [(size_t)Bb * Lt * HD];
__device__ __align__(1024) __half hB_V   [(size_t)Bb * HD * Lt];
__device__ __align__(1024) __half hB_wop [(size_t)DP * HH];
__device__ __align__(1024) __half hB_woe [(size_t)DE * HH];

__device__ __forceinline__ uint32_t s2u(const void* p) {
    uint32_t a;
    asm("{ .reg .u64 t; cvta.to.shared.u64 t, %1; cvt.u32.u64 %0, t; }" : "=r"(a) : "l"(p));
    return a;
}

#define CP_ASYNC16(saddr, gaddr) \
    asm volatile("cp.async.cg.shared.global [%0], [%1], 16;" :: "r"(saddr), "l"(gaddr))
#define CP_COMMIT() asm volatile("cp.async.commit_group;")
#define CP_WAIT(n)  asm volatile("cp.async.wait_group %0;" :: "n"(n))

#define LDSM4(r, addr)                                                       \
    asm volatile("ldmatrix.sync.aligned.m8n8.x4.shared.b16 {%0,%1,%2,%3}, [%4];" \
        : "=r"((r)[0]), "=r"((r)[1]), "=r"((r)[2]), "=r"((r)[3]) : "r"(addr))

#define MMA16816(c, a, b0, b1)                                               \
    asm volatile("mma.sync.aligned.m16n8k16.row.col.f32.f16.f16.f32 "        \
        "{%0,%1,%2,%3},{%4,%5,%6,%7},{%8,%9},{%0,%1,%2,%3};"                 \
        : "+f"((c)[0]), "+f"((c)[1]), "+f"((c)[2]), "+f"((c)[3])             \
        : "r"((a)[0]), "r"((a)[1]), "r"((a)[2]), "r"((a)[3]), "r"(b0), "r"(b1))

// ---------------------------------------------------------------------------
// Persistent multi-zone HMMA GEMM (TN): 128x128 tiles, BK=64, 8 warps of
// 32x64, 3-stage cp.async ring, XOR swizzle, batched A-fragment loads.
// Epilogue restages C through smem for fully coalesced global writes.
// ---------------------------------------------------------------------------
constexpr int GEMM_SMEM = 98304;

struct GZone {
    const __half* A; const __half* B; float* C; const float* mask;
    long long sAz, sBz, cso, csi, mzs;
    int K, zshB, czsh, ldc, use_mask, out_half, nt, mt, tstart;
    float scale;
};
struct GZones { GZone z[2]; int nz; int total; };

__global__ void __launch_bounds__(256, 2) gemm_hmma(GZones gz)
{
    extern __shared__ __align__(1024) char smem[];
    const uint32_t sbase = s2u(smem);
    float* scf = reinterpret_cast<float*>(smem);
    const int t = threadIdx.x;
    const int lrow = t >> 3, lc = t & 7;
    const int wid = t >> 5, lane = t & 31;
    const int wm = wid >> 1, wn = wid & 1;
    const int a_r = lane & 15, a_c = lane >> 4;
    const int b_r = (lane & 7) + ((lane >> 4) << 3), b_c = (lane >> 3) & 1;

    for (int tix = blockIdx.x; tix < gz.total; tix += gridDim.x) {
        const int zi = (gz.nz > 1 && tix >= gz.z[1].tstart) ? 1 : 0;
        const GZone& d = gz.z[zi];
        const int lt2 = tix - d.tstart;
        const int bx = lt2 % d.nt;
        const int tmp = lt2 / d.nt;
        const int by = tmp % d.mt, bz = tmp / d.mt;
        const int K = d.K;
        const int nch = K >> 6;

        const __half* Ag = d.A + (long long)bz * d.sAz + (long long)by * 128 * K;
        const __half* Bg = d.B + (long long)(bz >> d.zshB) * d.sBz + (long long)bx * 128 * K;

        float acc[2][8][4];
#pragma unroll
        for (int i = 0; i < 2; i++)
#pragma unroll
            for (int j = 0; j < 8; j++)
#pragma unroll
                for (int k = 0; k < 4; k++) acc[i][j][k] = 0.f;

#define STAGE(s, k0) do {                                                    \
    uint32_t _sA = sbase + (s) * 32768;                                      \
    uint32_t _sB = _sA + 16384;                                              \
    _Pragma("unroll")                                                        \
    for (int _i = 0; _i < 4; _i++) {                                         \
        int _r = lrow + _i * 32;                                             \
        uint32_t _sw = ((uint32_t)(lc ^ (_r & 7))) << 4;                     \
        CP_ASYNC16(_sA + _r * 128 + _sw, Ag + (long long)_r * K + (k0) + lc * 8); \
        CP_ASYNC16(_sB + _r * 128 + _sw, Bg + (long long)_r * K + (k0) + lc * 8); \
    }                                                                        \
    CP_COMMIT();                                                             \
} while (0)

        __syncthreads();  // smem reuse across tiles (ring + epilogue restage)
        STAGE(0, 0);
        if (nch > 1) STAGE(1, 64);

        int slot = 0, slot2 = (nch > 2) ? 2 : 0;
        for (int ch = 0; ch < nch; ch++) {
            if (ch + 1 < nch) CP_WAIT(1); else CP_WAIT(0);
            __syncthreads();
            if (ch + 2 < nch) {
                STAGE(slot2, (ch + 2) << 6);
                slot2 = (slot2 == 2) ? 0 : slot2 + 1;
            }
            uint32_t sA = sbase + slot * 32768;
            uint32_t sB = sA + 16384;
            slot = (slot == 2) ? 0 : slot + 1;

            uint32_t a[4][2][4];   // batched A fragments [ks][mt][regs]
#pragma unroll
            for (int ks = 0; ks < 4; ks++) {
                const int kc = ks << 1;
#pragma unroll
                for (int mt2 = 0; mt2 < 2; mt2++) {
                    int r = wm * 32 + mt2 * 16 + a_r;
                    LDSM4(a[ks][mt2], sA + r * 128 + ((uint32_t)((kc + a_c) ^ (r & 7)) << 4));
                }
            }
#pragma unroll
            for (int ks = 0; ks < 4; ks++) {
                const int kc = ks << 1;
                uint32_t b[4][4];
#pragma unroll
                for (int nt2 = 0; nt2 < 4; nt2++) {
                    int n = wn * 64 + nt2 * 16 + b_r;
                    LDSM4(b[nt2], sB + n * 128 + ((uint32_t)((kc + b_c) ^ (n & 7)) << 4));
                }
#pragma unroll
                for (int mt2 = 0; mt2 < 2; mt2++)
#pragma unroll
                    for (int nt = 0; nt < 8; nt++)
                        MMA16816(acc[mt2][nt], a[ks][mt2],
                                 b[nt >> 1][(nt & 1) * 2], b[nt >> 1][(nt & 1) * 2 + 1]);
            }
        }
#undef STAGE

        // ---- epilogue: restage through smem (128 x 132 padded) ----
        __syncthreads();
        const int g = lane >> 2, tig = lane & 3;
#pragma unroll
        for (int mt2 = 0; mt2 < 2; mt2++) {
#pragma unroll
            for (int h2 = 0; h2 < 2; h2++) {
                int row = wm * 32 + mt2 * 16 + g + h2 * 8;
                float* srow = scf + row * 132 + wn * 64 + tig * 2;
#pragma unroll
                for (int nt = 0; nt < 8; nt++) {
                    srow[nt * 8]     = acc[mt2][nt][h2 * 2 + 0];
                    srow[nt * 8 + 1] = acc[mt2][nt][h2 * 2 + 1];
                }
            }
        }
        __syncthreads();

        const long long coff = ((long long)(bz >> d.czsh)) * d.cso +
                               (long long)(bz & ((1 << d.czsh) - 1)) * d.csi;
        const long long cbase = (long long)by * 128 * d.ldc + (long long)bx * 128;

        if (d.out_half) {
            __half* cp = reinterpret_cast<__half*>(d.C) + coff + cbase;
#pragma unroll
            for (int j = 0; j < 8; j++) {
                int idx = j * 256 + t;        // uint4 index: 16 per row
                int r = idx >> 4, h8 = (idx & 15) * 8;
                const float* sr = scf + r * 132 + h8;
                __half2 q0 = __halves2half2(__float2half_rn(sr[0]), __float2half_rn(sr[1]));
                __half2 q1 = __halves2half2(__float2half_rn(sr[2]), __float2half_rn(sr[3]));
                __half2 q2 = __halves2half2(__float2half_rn(sr[4]), __float2half_rn(sr[5]));
                __half2 q3 = __halves2half2(__float2half_rn(sr[6]), __float2half_rn(sr[7]));
                uint4 w;
                w.x = *reinterpret_cast<uint32_t*>(&q0);
                w.y = *reinterpret_cast<uint32_t*>(&q1);
                w.z = *reinterpret_cast<uint32_t*>(&q2);
                w.w = *reinterpret_cast<uint32_t*>(&q3);
                *reinterpret_cast<uint4*>(cp + (long long)r * d.ldc + h8) = w;
            }
        } else {
            float* cp = d.C + coff + cbase;
            const float* mp = d.use_mask ? (d.mask + (long long)(bz >> 3) * d.mzs + cbase) : nullptr;
            const float sc = d.scale;
#pragma unroll
            for (int j = 0; j < 16; j++) {
                int idx = j * 256 + t;        // float4 index: 32 per row
                int r = idx >> 5, c4 = (idx & 31) * 4;
                const float* sr = scf + r * 132 + c4;
                float4 v = make_float4(sr[0], sr[1], sr[2], sr[3]);
                if (d.use_mask) {
                    float4 m = *reinterpret_cast<const float4*>(mp + (long long)r * d.ldc + c4);
                    v.x = v.x * sc + m.x; v.y = v.y * sc + m.y;
                    v.z = v.z * sc + m.z; v.w = v.w * sc + m.w;
                }
                *reinterpret_cast<float4*>(cp + (long long)r * d.ldc + c4) = v;
            }
        }
    }
}

// ---------------------------------------------------------------------------
// Megapack: embeds (direct fp16) + weights (smem transpose fp16)
// ---------------------------------------------------------------------------
struct Seg {
    const float* src; __half* dst;
    int nblocks; int mode; int R; int K;
};
struct SegTable { Seg s[10]; };

__global__ void __launch_bounds__(256) megapack(SegTable st)
{
    __shared__ float sm[32][33];
    int b = blockIdx.x, si = 0;
    while (b >= st.s[si].nblocks) { b -= st.s[si].nblocks; si++; }
    const Seg sg = st.s[si];

    if (sg.mode == 0) {
        long long idx = (long long)b * 256 + threadIdx.x;
        int K8 = sg.K >> 3;
        long long items = (long long)sg.R * K8;
        if (idx >= items) return;
        int kc = (int)(idx % K8);
        long long r = idx / K8;
        const float* sp = sg.src + r * (long long)sg.K + kc * 8;
        float4 x = *reinterpret_cast<const float4*>(sp);
        float4 y = *reinterpret_cast<const float4*>(sp + 4);
        float v[8] = {x.x, x.y, x.z, x.w, y.x, y.y, y.z, y.w};
        unsigned short o[8];
#pragma unroll
        for (int i = 0; i < 8; i++) o[i] = __half_as_ushort(__float2half_rn(v[i]));
        uint4 w;
        w.x = o[0] | ((uint32_t)o[1] << 16); w.y = o[2] | ((uint32_t)o[3] << 16);
        w.z = o[4] | ((uint32_t)o[5] << 16); w.w = o[6] | ((uint32_t)o[7] << 16);
        *reinterpret_cast<uint4*>(sg.dst + r * (long long)sg.K + kc * 8) = w;
    } else {
        int nx = sg.K >> 5;
        int k0 = (b % nx) * 32, n0 = (b / nx) * 32;
        int tx = threadIdx.x & 31, ty = threadIdx.x >> 5;
#pragma unroll
        for (int i = 0; i < 4; i++)
            sm[ty + 8 * i][tx] = sg.src[(long long)(k0 + ty + 8 * i) * sg.R + n0 + tx];
        __syncthreads();
#pragma unroll
        for (int i = 0; i < 4; i++) {
            int n = n0 + ty + 8 * i;
            sg.dst[(long long)n * sg.K + k0 + tx] = __float2half_rn(sm[tx][ty + 8 * i]);
        }
    }
}

// ---------------------------------------------------------------------------
// Fused RoPE + fp16 pack of Q (per b,h) and K (per b), from fp16 QKV
// ---------------------------------------------------------------------------
__global__ void __launch_bounds__(128) qkrope_pack(
    const __half* __restrict__ QKV, const int* __restrict__ pos,
    __half* __restrict__ aQ, __half* __restrict__ bK)
{
    const int bl = blockIdx.x;
    const int bidx = bl >> 10, l = bl & 1023;
    const int i = threadIdx.x;
    const float p = (float)pos[bl];
    const float inv = powf(10000.0f, -(float)i * (1.0f / 128.0f));
    float s, c;
    sincosf(p * inv, &s, &c);

    const __half* row = QKV + (long long)bl * NQKV;
#pragma unroll
    for (int h = 0; h < Hh; h++) {
        float x1 = __half2float(row[h * HD + i]);
        float x2 = __half2float(row[h * HD + 128 + i]);
        __half* q = aQ + (((long long)(bidx * Hh + h) * Lt + l) * HD);
        q[i]       = __float2half_rn(x1 * c - x2 * s);
        q[128 + i] = __float2half_rn(x2 * c + x1 * s);
    }
    float x1 = __half2float(row[HH + i]);
    float x2 = __half2float(row[HH + 128 + i]);
    __half* kd = bK + ((long long)bidx * Lt + l) * HD;
    kd[i]       = __float2half_rn(x1 * c - x2 * s);
    kd[128 + i] = __float2half_rn(x2 * c + x1 * s);
}

// ---------------------------------------------------------------------------
// V transpose-pack from fp16 QKV: bV[b][d][Lt]
// ---------------------------------------------------------------------------
__global__ void __launch_bounds__(256) vtpack(const __half* __restrict__ QKV,
                                              __half* __restrict__ bV)
{
    __shared__ __half sm[32][40];
    const int bidx = blockIdx.z;
    const int l0 = blockIdx.x * 32, d0 = blockIdx.y * 32;
    const int tx = threadIdx.x & 31, ty = threadIdx.x >> 5;
#pragma unroll
    for (int i = 0; i < 4; i++)
        sm[ty + 8 * i][tx] = QKV[((long long)bidx * Lt + l0 + ty + 8 * i) * NQKV + HH + HD + d0 + tx];
    __syncthreads();
#pragma unroll
    for (int i = 0; i < 4; i++) {
        int d = d0 + ty + 8 * i;
        bV[((long long)bidx * HD + d) * Lt + l0 + tx] = sm[tx][ty + 8 * i];
    }
}

// ---------------------------------------------------------------------------
// Softmax: warp-per-row, shuffle reductions only, __expf, float4 I/O.
// ---------------------------------------------------------------------------
__global__ void __launch_bounds__(256) softmax_pack(const float* __restrict__ S,
                                                    __half* __restrict__ P)
{
    const long long rowid = (long long)blockIdx.x * 8 + (threadIdx.x >> 5);
    const int lane = threadIdx.x & 31;
    const float* p = S + rowid * Lt + lane * 4;

    float v[32];
#pragma unroll
    for (int c = 0; c < 8; c++) {
        float4 x = *reinterpret_cast<const float4*>(p + c * 128);
        v[c * 4 + 0] = x.x; v[c * 4 + 1] = x.y; v[c * 4 + 2] = x.z; v[c * 4 + 3] = x.w;
    }

    float m = v[0];
#pragma unroll
    for (int i = 1; i < 32; i++) m = fmaxf(m, v[i]);
#pragma unroll
    for (int o = 16; o > 0; o >>= 1)
        m = fmaxf(m, __shfl_xor_sync(0xFFFFFFFFu, m, o));

    float sum = 0.f;
#pragma unroll
    for (int i = 0; i < 32; i++) { v[i] = __expf(v[i] - m); sum += v[i]; }
#pragma unroll
    for (int o = 16; o > 0; o >>= 1)
        sum += __shfl_xor_sync(0xFFFFFFFFu, sum, o);
    const float invs = 1.0f / sum;

    __half* dp = P + rowid * Lt + lane * 4;
#pragma unroll
    for (int c = 0; c < 8; c++) {
        __half2 h0 = __halves2half2(__float2half_rn(v[c * 4 + 0] * invs),
                                    __float2half_rn(v[c * 4 + 1] * invs));
        __half2 h1 = __halves2half2(__float2half_rn(v[c * 4 + 2] * invs),
                                    __float2half_rn(v[c * 4 + 3] * invs));
        uint2 w;
        w.x = *reinterpret_cast<uint32_t*>(&h0);
        w.y = *reinterpret_cast<uint32_t*>(&h1);
        *reinterpret_cast<uint2*>(dp + c * 128) = w;
    }
}

// ---------------------------------------------------------------------------
// Host
// ---------------------------------------------------------------------------
static GZone mkzone(const __half* A, const __half* B, void* C, const float* mask,
                    int nt, int mt, int K, long long sAz, long long sBz,
                    int zshB, long long cso, long long csi, int czsh, int ldc,
                    float scale, int use_mask, long long mzs, int out_half)
{
    GZone z;
    z.A = A; z.B = B; z.C = (float*)C; z.mask = mask;
    z.sAz = sAz; z.sBz = sBz; z.cso = cso; z.csi = csi; z.mzs = mzs;
    z.K = K; z.zshB = zshB; z.czsh = czsh; z.ldc = ldc;
    z.use_mask = use_mask; z.out_half = out_half;
    z.nt = nt; z.mt = mt; z.tstart = 0;
    z.scale = scale;
    return z;
}

static void launch_zones(GZone z0, int n0, GZone z1, int n1, int nz)
{
    GZones g;
    z0.tstart = 0;
    g.z[0] = z0;
    int total = n0;
    if (nz > 1) { z1.tstart = total; g.z[1] = z1; total += n1; }
    else        { g.z[1] = z0; }
    g.nz = nz; g.total = total;
    int grid = total < 296 ? total : 296;   // 148 SMs x 2 CTAs
    gemm_hmma<<<grid, 256, GEMM_SMEM>>>(g);
}

extern "C" void kernel_launch(void* const* d_in, const int* in_sizes, int n_in,
                              void* d_out, int out_size)
{
    const float* pali   = (const float*)d_in[0];
    const float* expert = (const float*)d_in[1];
    const int*   pos    = (const int*)d_in[2];
    const float* mask   = (const float*)d_in[3];
    const float* wq_p = (const float*)d_in[5];
    const float* wk_p = (const float*)d_in[6];
    const float* wv_p = (const float*)d_in[7];
    const float* wo_p = (const float*)d_in[8];
    const float* wq_e = (const float*)d_in[9];
    const float* wk_e = (const float*)d_in[10];
    const float* wv_e = (const float*)d_in[11];
    const float* wo_e = (const float*)d_in[12];
    float* out = (float*)d_out;

    cudaFuncSetAttribute(gemm_hmma, cudaFuncAttributeMaxDynamicSharedMemorySize, GEMM_SMEM);

    float* S;
    cudaGetSymbolAddress((void**)&S, g_S);
    __half *QKVh, *aP, *aE, *aQ, *aPP, *AO, *bQP, *bQE, *bK, *bV, *bWP, *bWE;
    cudaGetSymbolAddress((void**)&QKVh, hQKV);
    cudaGetSymbolAddress((void**)&aP,  hA_pali);
    cudaGetSymbolAddress((void**)&aE,  hA_exp);
    cudaGetSymbolAddress((void**)&aQ,  hA_Q);
    cudaGetSymbolAddress((void**)&aPP, hA_P);
    cudaGetSymbolAddress((void**)&AO,  hAO);
    cudaGetSymbolAddress((void**)&bQP, hB_qkvp);
    cudaGetSymbolAddress((void**)&bQE, hB_qkve);
    cudaGetSymbolAddress((void**)&bK,  hB_K);
    cudaGetSymbolAddress((void**)&bV,  hB_V);
    cudaGetSymbolAddress((void**)&bWP, hB_wop);
    cudaGetSymbolAddress((void**)&bWE, hB_woe);

    SegTable st;
    int nb = 0;
    auto setd = [&](int i, const float* s, __half* d, int R, int K) {
        st.s[i] = {s, d, (int)(((long long)R * K / 8 + 255) / 256), 0, R, K};
        nb += st.s[i].nblocks;
    };
    auto sett = [&](int i, const float* s, __half* d, int N, int K) {
        st.s[i] = {s, d, (K / 32) * (N / 32), 1, N, K};
        nb += st.s[i].nblocks;
    };
    setd(0, pali,   aP, Bb * LP, DP);
    setd(1, expert, aE, Bb * LE, DE);
    sett(2, wq_p, bQP,                      HH, DP);
    sett(3, wk_p, bQP + (long long)HH * DP,        HD, DP);
    sett(4, wv_p, bQP + (long long)(HH + HD) * DP, HD, DP);
    sett(5, wq_e, bQE,                      HH, DE);
    sett(6, wk_e, bQE + (long long)HH * DE,        HD, DE);
    sett(7, wv_e, bQE + (long long)(HH + HD) * DE, HD, DE);
    sett(8, wo_p, bWP, DP, HH);
    sett(9, wo_e, bWE, DE, HH);
    megapack<<<nb, 256>>>(st);  // launch 1

    // --- QKV projections (merged, fp16 output) ---  launch 2
    {
        GZone zp = mkzone(aP, bQP, QKVh, nullptr, NQKV / 128, LP / 128, DP,
                          (long long)LP * DP, 0, 31, (long long)Lt * NQKV, 0, 0, NQKV, 1.f, 0, 0, 1);
        GZone ze = mkzone(aE, bQE, QKVh + (long long)LP * NQKV, nullptr, NQKV / 128, LE / 128, DE,
                          (long long)LE * DE, 0, 31, (long long)Lt * NQKV, 0, 0, NQKV, 1.f, 0, 0, 1);
        launch_zones(zp, (NQKV / 128) * (LP / 128) * Bb, ze, (NQKV / 128) * (LE / 128) * Bb, 2);
    }

    // --- fused RoPE + Q/K pack ---  launch 3
    qkrope_pack<<<Bb * Lt, 128>>>(QKVh, pos, aQ, bK);

    // --- scores = scale*QK^T + mask ---  launch 4 (ncu-profiled slot)
    {
        GZone zs = mkzone(aQ, bK, S, mask, Lt / 128, Lt / 128, HD,
                          (long long)Lt * HD, (long long)Lt * HD, 3,
                          (long long)Lt * Lt, 0, 0, Lt, 0.0625f, 1, (long long)Lt * Lt, 0);
        launch_zones(zs, (Lt / 128) * (Lt / 128) * Bb * Hh, zs, 0, 1);
    }

    // --- V transpose-pack ---  launch 5
    {
        dim3 g(Lt / 32, HD / 32, Bb);
        vtpack<<<g, 256>>>(QKVh, bV);
    }

    // --- softmax -> fp16 P ---  launch 6
    softmax_pack<<<Bb * Hh * Lt / 8, 256>>>(S, aPP);

    // --- AO = P @ V (fp16 out) ---  launch 7
    {
        GZone zv = mkzone(aPP, bV, AO, nullptr, HD / 128, Lt / 128, Lt,
                          (long long)Lt * Lt, (long long)HD * Lt, 3,
                          (long long)Lt * HH, HD, 3, HH, 1.f, 0, 0, 1);
        launch_zones(zv, (HD / 128) * (Lt / 128) * Bb * Hh, zv, 0, 1);
    }

    // --- output projections (merged) ---  launch 8
    {
        GZone zo = mkzone(AO, bWP, out, nullptr, DP / 128, LP / 128, HH,
                          (long long)Lt * HH, 0, 31, (long long)LP * DP, 0, 0, DP, 1.f, 0, 0, 0);
        GZone ze = mkzone(AO + (long long)LP * HH, bWE, out + (long long)Bb * LP * DP, nullptr,
                          DE / 128, LE / 128, HH,
                          (long long)Lt * HH, 0, 31, (long long)LE * DE, 0, 0, DE, 1.f, 0, 0, 0);
        launch_zones(zo, (DP / 128) * (LP / 128) * Bb, ze, (DE / 128) * (LE / 128) * Bb, 2);
    }
}